// round 2
// baseline (speedup 1.0000x reference)
#include <cuda_runtime.h>
#include <math.h>

// Problem constants
#define BATCH    4096
#define T        80
#define EMB      100
#define H        256
#define HS       34          // padded SMEM stride for state tiles (even -> 8B alignable)
#define KC       16          // k-chunk for streamed weight tiles
#define M2       32          // batch rows per block
#define NTHREADS 256

// Streamed GEMM: acc[8][4] += hs(k-major [256][HS]) @ Wg([256][256] row-major),
// weights double-buffered through SMEM with register prefetch.
__device__ __forceinline__ void gemm_stream(
    const float* __restrict__ Wg,
    const float* __restrict__ hs,
    float* __restrict__ wbuf,
    float acc[8][4], int tid, int r0, int c0)
{
    const float4* W4 = (const float4*)Wg;
    float4 pre[4];
#pragma unroll
    for (int j = 0; j < 4; ++j) pre[j] = W4[tid + j * 256];

#pragma unroll 1
    for (int kt = 0; kt < H / KC; ++kt) {
        float* buf = wbuf + (kt & 1) * (KC * H);
        __syncthreads();                       // prior compute on this buffer done
#pragma unroll
        for (int j = 0; j < 4; ++j) ((float4*)buf)[tid + j * 256] = pre[j];
        __syncthreads();                       // tile visible
        if (kt < H / KC - 1) {
#pragma unroll
            for (int j = 0; j < 4; ++j)
                pre[j] = W4[(kt + 1) * (KC * H / 4) + tid + j * 256];
        }
        const float* hk = hs + kt * KC * HS;
#pragma unroll 8
        for (int kk = 0; kk < KC; ++kk) {
            float4 b = *(const float4*)&buf[kk * H + c0];
#pragma unroll
            for (int i = 0; i < 8; ++i) {
                float a = hk[kk * HS + r0 + i];
                acc[i][0] = fmaf(a, b.x, acc[i][0]);
                acc[i][1] = fmaf(a, b.y, acc[i][1]);
                acc[i][2] = fmaf(a, b.z, acc[i][2]);
                acc[i][3] = fmaf(a, b.w, acc[i][3]);
            }
        }
    }
}

__global__ __launch_bounds__(NTHREADS, 1)
void rnn_fused_kernel(const int*   __restrict__ inputs, // [BATCH][T]
                      const float* __restrict__ emb,    // [VOCAB][EMB]
                      const float* __restrict__ W1,     // [EMB][H]
                      const float* __restrict__ U1,     // [H][H]
                      const float* __restrict__ b1,     // [H]
                      const float* __restrict__ W2,     // [H][H]
                      const float* __restrict__ U2,     // [H][H]
                      const float* __restrict__ b2,     // [H]
                      float*       __restrict__ out)    // [BATCH][H]
{
    extern __shared__ float sm[];
    float* W1s  = sm;                    // EMB*H      = 25600 floats
    float* xs   = W1s + EMB * H;         // EMB*HS     =  3400
    float* h1   = xs + EMB * HS;         // H*HS       =  8704
    float* h2   = h1 + H * HS;           // H*HS       =  8704
    float* wbuf = h2 + H * HS;           // 2*KC*H     =  8192

    const int tid = threadIdx.x;
    const int ty = tid >> 6, tx = tid & 63;
    const int r0 = ty * 8, c0 = tx * 4;
    const int bb = blockIdx.x * M2;

    // Resident W1 load (25600 floats = 6400 float4; 25 per thread, exact)
    {
        const float4* s = (const float4*)W1;
        float4* d = (float4*)W1s;
#pragma unroll
        for (int j = 0; j < (EMB * H / 4) / NTHREADS; ++j)
            d[tid + j * NTHREADS] = s[tid + j * NTHREADS];
    }
    // Zero both states
    for (int i = tid; i < 2 * H * HS; i += NTHREADS) h1[i] = 0.f;

    const float4 b1v = ((const float4*)b1)[tx];
    const float4 b2v = ((const float4*)b2)[tx];
    __syncthreads();

#pragma unroll 1
    for (int t = 0; t < T; ++t) {
        // ---- gather x_t : 32 rows x 25 float4 from emb, store k-major ----
        for (int i = tid; i < M2 * (EMB / 4); i += NTHREADS) {
            int r  = i / (EMB / 4);
            int kq = i % (EMB / 4);
            int tok = inputs[(bb + r) * T + t];
            float4 v = ((const float4*)emb)[tok * (EMB / 4) + kq];
            xs[(kq * 4 + 0) * HS + r] = v.x;
            xs[(kq * 4 + 1) * HS + r] = v.y;
            xs[(kq * 4 + 2) * HS + r] = v.z;
            xs[(kq * 4 + 3) * HS + r] = v.w;
        }
        __syncthreads();

        // ---- layer 1: acc = b1 + x@W1 + h1_old@U1 ----
        float acc[8][4];
#pragma unroll
        for (int i = 0; i < 8; ++i) {
            acc[i][0] = b1v.x; acc[i][1] = b1v.y;
            acc[i][2] = b1v.z; acc[i][3] = b1v.w;
        }
#pragma unroll 4
        for (int k = 0; k < EMB; ++k) {
            float4 b = *(const float4*)&W1s[k * H + c0];
#pragma unroll
            for (int i = 0; i < 8; ++i) {
                float a = xs[k * HS + r0 + i];
                acc[i][0] = fmaf(a, b.x, acc[i][0]);
                acc[i][1] = fmaf(a, b.y, acc[i][1]);
                acc[i][2] = fmaf(a, b.z, acc[i][2]);
                acc[i][3] = fmaf(a, b.w, acc[i][3]);
            }
        }
        gemm_stream(U1, h1, wbuf, acc, tid, r0, c0);

        __syncthreads();                 // everyone done reading old h1
#pragma unroll
        for (int i = 0; i < 8; ++i)
#pragma unroll
            for (int j = 0; j < 4; ++j)
                h1[(c0 + j) * HS + (r0 + i)] = tanhf(acc[i][j]);
        __syncthreads();                 // new h1 visible

        // ---- layer 2: acc2 = b2 + h1_new@W2 + h2_old@U2 ----
        float acc2[8][4];
#pragma unroll
        for (int i = 0; i < 8; ++i) {
            acc2[i][0] = b2v.x; acc2[i][1] = b2v.y;
            acc2[i][2] = b2v.z; acc2[i][3] = b2v.w;
        }
        gemm_stream(W2, h1, wbuf, acc2, tid, r0, c0);
        gemm_stream(U2, h2, wbuf, acc2, tid, r0, c0);

        __syncthreads();                 // everyone done reading old h2
        if (t == T - 1) {
#pragma unroll
            for (int i = 0; i < 8; ++i) {
                float4 o;
                o.x = 1.f / (1.f + expf(-tanhf(acc2[i][0])));
                o.y = 1.f / (1.f + expf(-tanhf(acc2[i][1])));
                o.z = 1.f / (1.f + expf(-tanhf(acc2[i][2])));
                o.w = 1.f / (1.f + expf(-tanhf(acc2[i][3])));
                *(float4*)&out[(bb + r0 + i) * H + c0] = o;
            }
        } else {
#pragma unroll
            for (int i = 0; i < 8; ++i)
#pragma unroll
                for (int j = 0; j < 4; ++j)
                    h2[(c0 + j) * HS + (r0 + i)] = tanhf(acc2[i][j]);
            __syncthreads();             // new h2 visible before next step
        }
    }
}

extern "C" void kernel_launch(void* const* d_in, const int* in_sizes, int n_in,
                              void* d_out, int out_size)
{
    const int*   inputs = (const int*)  d_in[0];
    const float* emb    = (const float*)d_in[1];
    const float* W1     = (const float*)d_in[2];
    const float* U1     = (const float*)d_in[3];
    const float* b1     = (const float*)d_in[4];
    const float* W2     = (const float*)d_in[5];
    const float* U2     = (const float*)d_in[6];
    const float* b2     = (const float*)d_in[7];
    // d_in[8] = Wd, d_in[9] = bd : unused by the reference output
    float* out = (float*)d_out;

    const int smem_bytes =
        (EMB * H + EMB * HS + 2 * H * HS + 2 * KC * H) * (int)sizeof(float); // 218400

    cudaFuncSetAttribute(rnn_fused_kernel,
                         cudaFuncAttributeMaxDynamicSharedMemorySize, smem_bytes);

    rnn_fused_kernel<<<BATCH / M2, NTHREADS, smem_bytes>>>(
        inputs, emb, W1, U1, b1, W2, U2, b2, out);
}